// round 15
// baseline (speedup 1.0000x reference)
#include <cuda_runtime.h>
#include <cuda_bf16.h>
#include <math.h>

// ---------------- problem constants ----------------
#define D        128
#define NMAX     4096          // max overlap (actual ~2800)
#define KTOP     32
#define TAU_INV  10.0f
#define UMAX     131072        // user-id capacity for mark tables
#define GT       128           // gemm tile (M=N=128)
#define BUFC     160           // per-row candidate buffer capacity
#define C0       80.0f         // target expected candidates per row
#define CBS      256           // compaction chunk size
#define CMAXB    128           // max compaction chunks per pair

// smem tile geometry: 128 rows x 128 bf16, rows padded to 272B (conflict-free ldmatrix)
#define ROWB     272
#define TILEB    (128 * ROWB)
#define SMEMB    (2 * TILEB)

#define FXSCALE  4294967296.0   // 2^32 fixed-point scale for deterministic sums

// ---------------- device scratch ----------------
__device__ __nv_bfloat16 g_Zwb[3][(size_t)NMAX * D];  // weak  (j / N dim); rows>=N stay 0
__device__ __nv_bfloat16 g_Zsb[3][(size_t)NMAX * D];  // strong(i / M dim)
__device__ float        g_buf[3][NMAX][BUFC];
__device__ float        g_pos[3][NMAX];
__device__ int          g_cnt[3][NMAX];
__device__ int          g_flag[3][NMAX];
__device__ float        g_thp[3];
__device__ int          g_mark[2][UMAX];              // generation marks: 0 cart, 1 purchase
__device__ int          g_gen = 1;                    // current generation (bumped by k_select)
__device__ int          g_common[3][NMAX];
__device__ int          g_bcnt[3][CMAXB];
__device__ int          g_N[3];
__device__ unsigned long long g_lsum[3];              // fixed-point loss sums
__device__ int          g_done;                       // select blocks done

// ---------------- small helpers ----------------
__device__ __forceinline__ unsigned smem_u32(const void* p) {
    unsigned a;
    asm("{ .reg .u64 t; cvta.to.shared.u64 t, %1; cvt.u32.u64 %0, t; }"
        : "=r"(a) : "l"(p));
    return a;
}
// warp-local int64-vs-int32 detection: odd 32-bit words of an int64<2^31
// buffer are all zero. 4 loads/lane, L2-hits after first warp.
__device__ __forceinline__ int detect_is64(const int* u, int n) {
    int lane = threadIdx.x & 31;
    int limit = n < 128 ? n : 128;
    int bad = 0;
    for (int i = 1 + 2 * lane; i < limit; i += 64) bad |= u[i];
    return __all_sync(0xffffffffu, bad == 0);
}
__device__ __forceinline__ int get_user(const void* p, int i, int is64) {
    return is64 ? (int)((const long long*)p)[i] : ((const int*)p)[i];
}
__device__ __forceinline__ int in_set(int bm, int v, int gen) {
    unsigned uv = (unsigned)v;
    return (uv < (unsigned)UMAX) && (g_mark[bm][uv] == gen);
}
__device__ __forceinline__ void pair_src(int p, const void* uw0, int n0,
                                         const void* uw1, int n1,
                                         const void* uw2, int n2,
                                         const void*& uw, int& nw, int& bm) {
    uw = p == 0 ? uw0 : (p == 1 ? uw1 : uw2);
    nw = p == 0 ? n0  : (p == 1 ? n1  : n2);
    bm = p == 0 ? 0 : 1;
}

// ---------------- build membership marks (no zeroing needed) ----------------
__global__ void k_build(const void* __restrict__ uc, int nc,
                        const void* __restrict__ up, int npv) {
    int is64 = detect_is64((const int*)uc, nc);
    int gen = g_gen;
    int i = blockIdx.x * blockDim.x + threadIdx.x;
    if (i < nc) {
        unsigned v = (unsigned)get_user(uc, i, is64);
        if (v < (unsigned)UMAX) g_mark[0][v] = gen;
    }
    if (i < npv) {
        unsigned v = (unsigned)get_user(up, i, is64);
        if (v < (unsigned)UMAX) g_mark[1][v] = gen;
    }
}

// ---------------- compaction: per-chunk counts ----------------
__global__ void __launch_bounds__(CBS)
k_ccount(const void* uw0, int n0, const void* uw1, int n1,
         const void* uw2, int n2) {
    __shared__ int ws[CBS / 32];
    int p = blockIdx.y;
    const void* uw; int nw, bm;
    pair_src(p, uw0, n0, uw1, n1, uw2, n2, uw, nw, bm);
    int is64 = detect_is64((const int*)uw0, n0);
    int gen = g_gen;
    int i = blockIdx.x * CBS + threadIdx.x;
    int flag = (i < nw) ? in_set(bm, get_user(uw, i, is64), gen) : 0;
    unsigned b = __ballot_sync(0xffffffffu, flag);
    int lane = threadIdx.x & 31, wid = threadIdx.x >> 5;
    if (lane == 0) ws[wid] = __popc(b);
    __syncthreads();
    if (threadIdx.x == 0) {
        int s = 0;
        #pragma unroll
        for (int w = 0; w < CBS / 32; w++) s += ws[w];
        g_bcnt[p][blockIdx.x] = s;
    }
}

// ---- stable write + N/theta (warp-shuffle prefix) + scratch zeroing ----
__global__ void __launch_bounds__(CBS)
k_cwrite(const void* uw0, int n0, const void* uw1, int n1,
         const void* uw2, int n2, int nblk) {
    __shared__ int ws[CBS / 32];
    __shared__ int wo[CBS / 32];
    __shared__ int blkbase;
    int p = blockIdx.y;
    int tid = threadIdx.x;
    const void* uw; int nw, bm;
    pair_src(p, uw0, n0, uw1, n1, uw2, n2, uw, nw, bm);
    int is64 = detect_is64((const int*)uw0, n0);
    int gen = g_gen;
    int i = blockIdx.x * CBS + tid;
    int v = 0, flag = 0;
    if (i < nw) { v = get_user(uw, i, is64); flag = in_set(bm, v, gen); }
    unsigned b = __ballot_sync(0xffffffffu, flag);
    int lane = tid & 31, wid = tid >> 5;
    int wp = __popc(b & ((1u << lane) - 1));
    if (lane == 0) ws[wid] = __popc(b);

    // zero gemm/select scratch (distributed over all cwrite blocks)
    {
        int nb_all = gridDim.x * gridDim.y;
        int bid = blockIdx.y * gridDim.x + blockIdx.x;
        for (int q = bid * CBS + tid; q < 3 * NMAX; q += nb_all * CBS) {
            ((int*)g_cnt)[q] = 0;
            ((int*)g_flag)[q] = 0;
        }
        if (bid == 0) {
            if (tid < 3) g_lsum[tid] = 0ull;
            if (tid == 3) g_done = 0;
        }
    }

    // warp 0: prefix base (chunks < blockIdx.x) and, for block 0, total/N/theta
    if (wid == 0) {
        int baseacc = 0, totacc = 0;
        for (int q = lane; q < nblk; q += 32) {
            int c = g_bcnt[p][q];
            totacc += c;
            if (q < (int)blockIdx.x) baseacc += c;
        }
        #pragma unroll
        for (int o = 16; o; o >>= 1) {
            baseacc += __shfl_xor_sync(0xffffffffu, baseacc, o);
            totacc  += __shfl_xor_sync(0xffffffffu, totacc, o);
        }
        if (lane == 0) {
            blkbase = baseacc;
            if (blockIdx.x == 0) {
                int N = totacc > NMAX ? NMAX : totacc;
                g_N[p] = N;
                float th = -1e30f;
                if (N > BUFC) {
                    float sigma = TAU_INV / sqrtf((float)D);
                    th = sigma * 1.4142136f * erfinvf(1.0f - (2.0f * C0) / (float)N);
                }
                g_thp[p] = th;
            }
        }
    }
    if (tid == 0) {
        int s = 0;
        #pragma unroll
        for (int w = 0; w < CBS / 32; w++) { wo[w] = s; s += ws[w]; }
    }
    __syncthreads();
    int pos = blkbase + wo[wid] + wp;
    if (flag && pos < NMAX) g_common[p][pos] = v;
}

// ---------------- gather + L2 normalize -> bf16 ----------------
__global__ void __launch_bounds__(256)
k_gather(const float* ev, const float* ec, const float* ep) {
    int p = blockIdx.y;
    const float* ew = p == 0 ? ev : (p == 1 ? ec : ev);
    const float* es = p == 0 ? ec : ep;
    int N = g_N[p];
    int lane = threadIdx.x & 31;
    int row  = blockIdx.x * 8 + (threadIdx.x >> 5);
    if (row >= N) return;
    int u = g_common[p][row];
    {
        float4 a = ((const float4*)(ew + (size_t)u * D))[lane];
        float ss = a.x * a.x + a.y * a.y + a.z * a.z + a.w * a.w;
        #pragma unroll
        for (int o = 16; o; o >>= 1) ss += __shfl_xor_sync(0xffffffffu, ss, o);
        float inv = 1.0f / fmaxf(sqrtf(ss), 1e-12f);
        __nv_bfloat162 lo = __floats2bfloat162_rn(a.x * inv, a.y * inv);
        __nv_bfloat162 hi = __floats2bfloat162_rn(a.z * inv, a.w * inv);
        ((uint2*)(g_Zwb[p] + (size_t)row * D))[lane] =
            make_uint2(*(unsigned*)&lo, *(unsigned*)&hi);
    }
    {
        float4 a = ((const float4*)(es + (size_t)u * D))[lane];
        float ss = a.x * a.x + a.y * a.y + a.z * a.z + a.w * a.w;
        #pragma unroll
        for (int o = 16; o; o >>= 1) ss += __shfl_xor_sync(0xffffffffu, ss, o);
        float inv = 1.0f / fmaxf(sqrtf(ss), 1e-12f);
        __nv_bfloat162 lo = __floats2bfloat162_rn(a.x * inv, a.y * inv);
        __nv_bfloat162 hi = __floats2bfloat162_rn(a.z * inv, a.w * inv);
        ((uint2*)(g_Zsb[p] + (size_t)row * D))[lane] =
            make_uint2(*(unsigned*)&lo, *(unsigned*)&hi);
    }
}

// ---------------- mma.sync helpers (base PTX ISA) ----------------
__device__ __forceinline__ void ldmx4(unsigned& r0, unsigned& r1,
                                      unsigned& r2, unsigned& r3, unsigned a) {
    asm volatile("ldmatrix.sync.aligned.m8n8.x4.shared.b16 {%0,%1,%2,%3}, [%4];"
                 : "=r"(r0), "=r"(r1), "=r"(r2), "=r"(r3) : "r"(a));
}
__device__ __forceinline__ void mma_bf16(float* c, const unsigned* a,
                                         unsigned b0, unsigned b1) {
    asm volatile(
        "mma.sync.aligned.m16n8k16.row.col.f32.bf16.bf16.f32 "
        "{%0,%1,%2,%3}, {%4,%5,%6,%7}, {%8,%9}, {%0,%1,%2,%3};"
        : "+f"(c[0]), "+f"(c[1]), "+f"(c[2]), "+f"(c[3])
        : "r"(a[0]), "r"(a[1]), "r"(a[2]), "r"(a[3]), "r"(b0), "r"(b1));
}

// ---------------- HMMA GEMM (chunked tiles, A-tile reuse) + fused epilogue ----
__global__ void __launch_bounds__(256) k_gemm_mma() {
    extern __shared__ __align__(16) char smem[];
    char* smA = smem;
    char* smB = smem + TILEB;
    unsigned sA = smem_u32(smA);
    unsigned sB = sA + TILEB;

    int tid = threadIdx.x;
    int lane = tid & 31, wid = tid >> 5;
    int warp_m = wid >> 1;
    int warp_n = wid & 1;

    int nb0 = (g_N[0] + GT - 1) >> 7, nt0 = nb0 * nb0;
    int nb1 = (g_N[1] + GT - 1) >> 7, nt1 = nb1 * nb1;
    int nb2 = (g_N[2] + GT - 1) >> 7, nt2 = nb2 * nb2;
    int total = nt0 + nt1 + nt2;

    // contiguous chunk of tiles per CTA (i-major order -> consecutive tiles
    // usually share the A tile)
    int chunk = (total + gridDim.x - 1) / (int)gridDim.x;
    int tbeg = blockIdx.x * chunk;
    int tend = tbeg + chunk; if (tend > total) tend = total;

    int a_row = ((lane >> 3) & 1) * 8 + (lane & 7);
    int a_kof = (lane >> 4) * 8;
    int b_row = ((lane >> 4) << 3) + (lane & 7);
    int b_kof = ((lane >> 3) & 1) * 8;

    int prev_key = -1;
    for (int t = tbeg; t < tend; t++) {
        int p, tt, nb;
        if (t < nt0)            { p = 0; tt = t;             nb = nb0; }
        else if (t < nt0 + nt1) { p = 1; tt = t - nt0;       nb = nb1; }
        else                    { p = 2; tt = t - nt0 - nt1; nb = nb2; }
        int N = g_N[p];
        int i0 = (tt / nb) << 7;
        int j0 = (tt % nb) << 7;
        const __nv_bfloat16* Zs = g_Zsb[p];
        const __nv_bfloat16* Zw = g_Zwb[p];

        int key = (p << 20) | i0;
        bool loadA = (key != prev_key);
        prev_key = key;

        #pragma unroll
        for (int q = tid; q < 2048; q += 256) {
            int row = q >> 4, ch = q & 15;
            if (loadA)
                *(uint4*)(smA + row * ROWB + ch * 16) =
                    *(const uint4*)(Zs + (size_t)(i0 + row) * D + ch * 8);
            *(uint4*)(smB + row * ROWB + ch * 16) =
                *(const uint4*)(Zw + (size_t)(j0 + row) * D + ch * 8);
        }
        __syncthreads();

        float c[2][8][4];
        #pragma unroll
        for (int mf = 0; mf < 2; mf++)
            #pragma unroll
            for (int nf = 0; nf < 8; nf++)
                #pragma unroll
                for (int r = 0; r < 4; r++) c[mf][nf][r] = 0.0f;

        unsigned aBase = sA + (warp_m * 32 + a_row) * ROWB + a_kof * 2;
        unsigned bBase = sB + (warp_n * 64 + b_row) * ROWB + b_kof * 2;

        #pragma unroll
        for (int ks = 0; ks < 8; ks++) {
            unsigned kb = ks * 32;
            unsigned a0[4], a1[4];
            ldmx4(a0[0], a0[1], a0[2], a0[3], aBase + kb);
            ldmx4(a1[0], a1[1], a1[2], a1[3], aBase + 16 * ROWB + kb);
            unsigned bf[8][2];
            #pragma unroll
            for (int bg = 0; bg < 4; bg++) {
                unsigned r0, r1, r2, r3;
                ldmx4(r0, r1, r2, r3, bBase + bg * 16 * ROWB + kb);
                bf[bg * 2 + 0][0] = r0; bf[bg * 2 + 0][1] = r1;
                bf[bg * 2 + 1][0] = r2; bf[bg * 2 + 1][1] = r3;
            }
            #pragma unroll
            for (int nf = 0; nf < 8; nf++) {
                mma_bf16(c[0][nf], a0, bf[nf][0], bf[nf][1]);
                mma_bf16(c[1][nf], a1, bf[nf][0], bf[nf][1]);
            }
        }
        __syncthreads();

        float th = g_thp[p];
        int mrow = lane >> 2;
        int ncol = (lane & 3) * 2;
        #pragma unroll
        for (int mf = 0; mf < 2; mf++) {
            #pragma unroll
            for (int nf = 0; nf < 8; nf++) {
                #pragma unroll
                for (int r = 0; r < 4; r++) {
                    int ig = i0 + warp_m * 32 + mf * 16 + mrow + ((r >> 1) << 3);
                    int jg = j0 + warp_n * 64 + nf * 8 + ncol + (r & 1);
                    if (ig >= N || jg >= N) continue;
                    float v = c[mf][nf][r] * TAU_INV;
                    if (jg == ig) g_pos[p][ig] = v;
                    else if (v >= th) {
                        int q = atomicAdd(&g_cnt[p][ig], 1);
                        if (q < BUFC) g_buf[p][ig][q] = v; else g_flag[p][ig] = 1;
                    }
                }
            }
        }
    }
}

// ---------------- sorted-descending register insert ----------------
#define TK_INSERT(T, v)                                   \
    do { float _v = (v);                                  \
        _Pragma("unroll")                                 \
        for (int _k = 0; _k < KTOP; _k++) {               \
            float _t = T[_k];                             \
            T[_k] = fmaxf(_t, _v);                        \
            _v = fminf(_t, _v);                           \
        }                                                 \
    } while (0)

// ---- select + inline fallback + fused deterministic fixed-point reduction ----
__global__ void __launch_bounds__(256) k_select(float* __restrict__ out) {
    __shared__ long long ssum[256];
    __shared__ int flist[256];
    __shared__ int fcnt;
    int p = blockIdx.y;
    int N = g_N[p];
    int tid = threadIdx.x;
    int i = blockIdx.x * 256 + tid;
    if (tid == 0) fcnt = 0;
    __syncthreads();

    long long my = 0;
    if (i < N) {
        int cnt = g_cnt[p][i];
        bool bad = g_flag[p][i] || cnt > BUFC || (cnt < KTOP && cnt < N - 1);
        if (bad) {
            int q = atomicAdd(&fcnt, 1);
            flist[q] = i;
        } else {
            const float* buf = g_buf[p][i];
            float T[KTOP];
            #pragma unroll
            for (int k = 0; k < KTOP; k++) T[k] = -INFINITY;
            for (int q = 0; q < cnt; q++) {
                float v = buf[q];
                if (v > T[KTOP - 1]) TK_INSERT(T, v);
            }
            float pos = g_pos[p][i];
            float m = fmaxf(pos, T[0]);
            float s = expf(pos - m);
            #pragma unroll
            for (int k = 0; k < KTOP; k++) s += expf(T[k] - m);
            float loss = m + logf(s) - pos;
            my = __double2ll_rn((double)loss * FXSCALE);
        }
    }
    __syncthreads();

    // warp-per-row exact recompute for flagged rows (expected: none)
    int nf = fcnt;
    int lane = tid & 31, wid = tid >> 5;
    for (int q = wid; q < nf; q += 8) {
        int i2 = flist[q];
        uint2 rs = ((const uint2*)(g_Zsb[p] + (size_t)i2 * D))[lane];
        __nv_bfloat162 s0 = *(__nv_bfloat162*)&rs.x, s1 = *(__nv_bfloat162*)&rs.y;
        float a0 = __low2float(s0), a1 = __high2float(s0);
        float a2 = __low2float(s1), a3 = __high2float(s1);
        float T[KTOP];
        #pragma unroll
        for (int k = 0; k < KTOP; k++) T[k] = -INFINITY;
        float pos = 0.0f;
        for (int j = 0; j < N; j++) {
            uint2 rw = ((const uint2*)(g_Zwb[p] + (size_t)j * D))[lane];
            __nv_bfloat162 w0 = *(__nv_bfloat162*)&rw.x, w1 = *(__nv_bfloat162*)&rw.y;
            float d = a0 * __low2float(w0) + a1 * __high2float(w0)
                    + a2 * __low2float(w1) + a3 * __high2float(w1);
            #pragma unroll
            for (int o = 16; o; o >>= 1) d += __shfl_xor_sync(0xffffffffu, d, o);
            d *= TAU_INV;
            if (j == i2) pos = d;
            else if (d > T[KTOP - 1]) TK_INSERT(T, d);
        }
        float m = fmaxf(pos, T[0]);
        float s = expf(pos - m);
        #pragma unroll
        for (int k = 0; k < KTOP; k++) s += expf(T[k] - m);
        if (lane == 0) {
            float loss = m + logf(s) - pos;
            my += __double2ll_rn((double)loss * FXSCALE);
        }
    }

    // block-wide integer reduction (deterministic) + one atomic per block
    ssum[tid] = my;
    __syncthreads();
    for (int o = 128; o; o >>= 1) {
        if (tid < o) ssum[tid] += ssum[tid + o];
        __syncthreads();
    }
    if (tid == 0) {
        if (ssum[0] != 0) atomicAdd(&g_lsum[p], (unsigned long long)ssum[0]);
        __threadfence();
        int nblocks = gridDim.x * gridDim.y;
        if (atomicAdd(&g_done, 1) == nblocks - 1) {
            __threadfence();
            double acc = 0.0;
            const double wgt[3] = {0.2, 1.0, 1.0};
            for (int q = 0; q < 3; q++) {
                int Nq = g_N[q];
                if (Nq >= 4)
                    acc += wgt[q] * ((double)(long long)g_lsum[q] / FXSCALE / (double)Nq);
            }
            out[0] = (float)acc;
            g_gen = g_gen + 1;     // next execution uses a fresh generation
            __threadfence();
        }
    }
}

// ---------------- launch ----------------
extern "C" void kernel_launch(void* const* d_in, const int* in_sizes, int n_in,
                              void* d_out, int out_size) {
    const float* ev = (const float*)d_in[0];
    const float* ec = (const float*)d_in[1];
    const float* ep = (const float*)d_in[2];
    const void*  uv = d_in[3]; int nv  = in_sizes[3];
    const void*  uc = d_in[4]; int nc  = in_sizes[4];
    const void*  up = d_in[5]; int np_ = in_sizes[5];

    int nwmax = nv > nc ? nv : nc; if (np_ > nwmax) nwmax = np_;
    int nbuild = nc > np_ ? nc : np_;
    int nblk = (nwmax + CBS - 1) / CBS; if (nblk > CMAXB) nblk = CMAXB;

    static int attr_done = 0;
    if (!attr_done) {
        cudaFuncSetAttribute(k_gemm_mma,
                             cudaFuncAttributeMaxDynamicSharedMemorySize, SMEMB);
        attr_done = 1;
    }

    // pairs: (view->cart), (cart->purchase), (view->purchase)
    k_build<<<(nbuild + 255) / 256, 256>>>(uc, nc, up, np_);
    k_ccount<<<dim3(nblk, 3), CBS>>>(uv, nv, uc, nc, uv, nv);
    k_cwrite<<<dim3(nblk, 3), CBS>>>(uv, nv, uc, nc, uv, nv, nblk);
    k_gather<<<dim3(NMAX / 8, 3), 256>>>(ev, ec, ep);
    k_gemm_mma<<<296, 256, SMEMB>>>();
    k_select<<<dim3(NMAX / 256, 3), 256>>>((float*)d_out);
}

// round 17
// speedup vs baseline: 1.1625x; 1.1625x over previous
#include <cuda_runtime.h>
#include <cuda_bf16.h>
#include <math.h>

// ---------------- problem constants ----------------
#define D        128
#define NMAX     4096          // max overlap (actual ~2800)
#define KTOP     32
#define TAU_INV  10.0f
#define BITW     4096          // 4096*32 bits >= U=100000
#define GT       128           // gemm tile (M=N=128)
#define BUFC     160           // per-row candidate buffer capacity
#define C0       80.0f         // target expected candidates per row
#define CBS      256           // compaction chunk size

// smem tile geometry: 128 rows x 128 bf16, rows padded to 272B (conflict-free ldmatrix)
#define ROWB     272
#define TILEB    (128 * ROWB)
#define SMEMB    (2 * TILEB)

#define FXSCALE  4294967296.0   // 2^32 fixed-point scale for deterministic sums

// ---------------- device scratch ----------------
__device__ __nv_bfloat16 g_Zwb[3][(size_t)NMAX * D];  // weak  (j / N dim); rows>=N stay 0
__device__ __nv_bfloat16 g_Zsb[3][(size_t)NMAX * D];  // strong(i / M dim)
__device__ float        g_buf[3][NMAX][BUFC];
__device__ float        g_pos[3][NMAX];
__device__ int          g_cnt[3][NMAX];
__device__ int          g_flag[3][NMAX];
__device__ unsigned int g_bitmap[2][BITW];            // 0: cart, 1: purchase
__device__ int          g_common[3][NMAX];
__device__ int          g_N[3];                       // atomic-reserved counts
__device__ int          g_is64;
__device__ unsigned long long g_lsum[3];              // fixed-point loss sums
__device__ int          g_done;                       // select blocks done

// ---------------- small helpers ----------------
__device__ __forceinline__ unsigned smem_u32(const void* p) {
    unsigned a;
    asm("{ .reg .u64 t; cvta.to.shared.u64 t, %1; cvt.u32.u64 %0, t; }"
        : "=r"(a) : "l"(p));
    return a;
}
__device__ __forceinline__ int get_user(const void* p, int i) {
    return g_is64 ? (int)((const long long*)p)[i] : ((const int*)p)[i];
}
__device__ __forceinline__ int in_set(int bm, int v) {
    unsigned uv = (unsigned)v;
    return (uv < BITW * 32u) && ((g_bitmap[bm][uv >> 5] >> (uv & 31)) & 1u);
}
__device__ __forceinline__ int clampN(int n) { return n > NMAX ? NMAX : n; }
__device__ __forceinline__ float theta_of(int N) {
    if (N <= BUFC) return -1e30f;                 // collect all negatives
    float sigma = TAU_INV / sqrtf((float)D);      // sim/tau std for unit vectors
    return sigma * 1.4142136f * erfinvf(1.0f - (2.0f * C0) / (float)N);
}

// ---------------- zero scratch + int64 detect (fused; R10-proven) ----------------
__global__ void k_zero(const int* __restrict__ u, int n) {
    int t = blockIdx.x * blockDim.x + threadIdx.x;
    int stride = gridDim.x * blockDim.x;
    for (int i = t; i < 2 * BITW; i += stride) ((unsigned*)g_bitmap)[i] = 0u;
    for (int i = t; i < 3 * NMAX; i += stride) { ((int*)g_cnt)[i] = 0; ((int*)g_flag)[i] = 0; }
    if (t < 3) { g_N[t] = 0; g_lsum[t] = 0ull; }
    if (t == 3) g_done = 0;
    if (blockIdx.x == 0) {
        __shared__ int nz;
        if (threadIdx.x == 0) nz = 0;
        __syncthreads();
        int limit = n < 128 ? n : 128;
        for (int i = 1 + 2 * (int)threadIdx.x; i < limit; i += 2 * (int)blockDim.x)
            if (u[i] != 0) atomicAdd(&nz, 1);
        __syncthreads();
        if (threadIdx.x == 0) g_is64 = (nz == 0) ? 1 : 0;
    }
}

__global__ void k_build(const void* __restrict__ uc, int nc,
                        const void* __restrict__ up, int npv) {
    int i = blockIdx.x * blockDim.x + threadIdx.x;
    if (i < nc) {
        unsigned v = (unsigned)get_user(uc, i);
        if (v < BITW * 32u) atomicOr(&g_bitmap[0][v >> 5], 1u << (v & 31));
    }
    if (i < npv) {
        unsigned v = (unsigned)get_user(up, i);
        if (v < BITW * 32u) atomicOr(&g_bitmap[1][v >> 5], 1u << (v & 31));
    }
}

// ------- single-pass UNORDERED compaction (loss is order-invariant) -------
__global__ void __launch_bounds__(CBS)
k_compact(const void* uw0, int n0, const void* uw1, int n1,
          const void* uw2, int n2) {
    __shared__ int wbase[CBS / 32];
    int p = blockIdx.y;
    const void* uw = p == 0 ? uw0 : (p == 1 ? uw1 : uw2);
    int nw         = p == 0 ? n0  : (p == 1 ? n1  : n2);
    int bm         = p == 0 ? 0 : 1;
    int tid = threadIdx.x, lane = tid & 31, wid = tid >> 5;
    int i = blockIdx.x * CBS + tid;
    int v = 0, flag = 0;
    if (i < nw) { v = get_user(uw, i); flag = in_set(bm, v); }
    unsigned b = __ballot_sync(0xffffffffu, flag);
    int wcnt = __popc(b);
    int wp = __popc(b & ((1u << lane) - 1));
    if (lane == 0 && wcnt) wbase[wid] = atomicAdd(&g_N[p], wcnt);
    __syncwarp();
    if (flag) {
        int pos = wbase[wid] + wp;
        if (pos < NMAX) g_common[p][pos] = v;
    }
}

// ---------------- gather + L2 normalize -> bf16 (R10-proven) ----------------
__global__ void __launch_bounds__(256)
k_gather(const float* ev, const float* ec, const float* ep) {
    int p = blockIdx.y;
    const float* ew = p == 0 ? ev : (p == 1 ? ec : ev);
    const float* es = p == 0 ? ec : ep;
    int N = clampN(g_N[p]);
    int lane = threadIdx.x & 31;
    int row  = blockIdx.x * 8 + (threadIdx.x >> 5);
    if (row >= N) return;
    int u = g_common[p][row];
    {
        float4 a = ((const float4*)(ew + (size_t)u * D))[lane];
        float ss = a.x * a.x + a.y * a.y + a.z * a.z + a.w * a.w;
        #pragma unroll
        for (int o = 16; o; o >>= 1) ss += __shfl_xor_sync(0xffffffffu, ss, o);
        float inv = 1.0f / fmaxf(sqrtf(ss), 1e-12f);
        __nv_bfloat162 lo = __floats2bfloat162_rn(a.x * inv, a.y * inv);
        __nv_bfloat162 hi = __floats2bfloat162_rn(a.z * inv, a.w * inv);
        ((uint2*)(g_Zwb[p] + (size_t)row * D))[lane] =
            make_uint2(*(unsigned*)&lo, *(unsigned*)&hi);
    }
    {
        float4 a = ((const float4*)(es + (size_t)u * D))[lane];
        float ss = a.x * a.x + a.y * a.y + a.z * a.z + a.w * a.w;
        #pragma unroll
        for (int o = 16; o; o >>= 1) ss += __shfl_xor_sync(0xffffffffu, ss, o);
        float inv = 1.0f / fmaxf(sqrtf(ss), 1e-12f);
        __nv_bfloat162 lo = __floats2bfloat162_rn(a.x * inv, a.y * inv);
        __nv_bfloat162 hi = __floats2bfloat162_rn(a.z * inv, a.w * inv);
        ((uint2*)(g_Zsb[p] + (size_t)row * D))[lane] =
            make_uint2(*(unsigned*)&lo, *(unsigned*)&hi);
    }
}

// ---------------- mma.sync helpers (base PTX ISA) ----------------
__device__ __forceinline__ void ldmx4(unsigned& r0, unsigned& r1,
                                      unsigned& r2, unsigned& r3, unsigned a) {
    asm volatile("ldmatrix.sync.aligned.m8n8.x4.shared.b16 {%0,%1,%2,%3}, [%4];"
                 : "=r"(r0), "=r"(r1), "=r"(r2), "=r"(r3) : "r"(a));
}
__device__ __forceinline__ void mma_bf16(float* c, const unsigned* a,
                                         unsigned b0, unsigned b1) {
    asm volatile(
        "mma.sync.aligned.m16n8k16.row.col.f32.bf16.bf16.f32 "
        "{%0,%1,%2,%3}, {%4,%5,%6,%7}, {%8,%9}, {%0,%1,%2,%3};"
        : "+f"(c[0]), "+f"(c[1]), "+f"(c[2]), "+f"(c[3])
        : "r"(a[0]), "r"(a[1]), "r"(a[2]), "r"(a[3]), "r"(b0), "r"(b1));
}

// -------- HMMA GEMM (R10 strided loop) + fused threshold epilogue --------
__global__ void __launch_bounds__(256) k_gemm_mma() {
    extern __shared__ __align__(16) char smem[];
    char* smA = smem;
    char* smB = smem + TILEB;
    unsigned sA = smem_u32(smA);
    unsigned sB = sA + TILEB;

    int tid = threadIdx.x;
    int lane = tid & 31, wid = tid >> 5;
    int warp_m = wid >> 1;
    int warp_n = wid & 1;

    int Narr[3]; float tharr[3];
    #pragma unroll
    for (int q = 0; q < 3; q++) {
        Narr[q] = clampN(g_N[q]);
        tharr[q] = theta_of(Narr[q]);
    }
    int nb0 = (Narr[0] + GT - 1) >> 7, nt0 = nb0 * nb0;
    int nb1 = (Narr[1] + GT - 1) >> 7, nt1 = nb1 * nb1;
    int nb2 = (Narr[2] + GT - 1) >> 7, nt2 = nb2 * nb2;
    int total = nt0 + nt1 + nt2;

    int a_row = ((lane >> 3) & 1) * 8 + (lane & 7);
    int a_kof = (lane >> 4) * 8;
    int b_row = ((lane >> 4) << 3) + (lane & 7);
    int b_kof = ((lane >> 3) & 1) * 8;

    for (int t = blockIdx.x; t < total; t += gridDim.x) {
        int p, tt, nb;
        if (t < nt0)            { p = 0; tt = t;             nb = nb0; }
        else if (t < nt0 + nt1) { p = 1; tt = t - nt0;       nb = nb1; }
        else                    { p = 2; tt = t - nt0 - nt1; nb = nb2; }
        int N = Narr[p];
        int i0 = (tt / nb) << 7;
        int j0 = (tt % nb) << 7;
        const __nv_bfloat16* Zs = g_Zsb[p];
        const __nv_bfloat16* Zw = g_Zwb[p];

        #pragma unroll
        for (int q = tid; q < 2048; q += 256) {
            int row = q >> 4, ch = q & 15;
            *(uint4*)(smA + row * ROWB + ch * 16) =
                *(const uint4*)(Zs + (size_t)(i0 + row) * D + ch * 8);
            *(uint4*)(smB + row * ROWB + ch * 16) =
                *(const uint4*)(Zw + (size_t)(j0 + row) * D + ch * 8);
        }
        __syncthreads();

        float c[2][8][4];
        #pragma unroll
        for (int mf = 0; mf < 2; mf++)
            #pragma unroll
            for (int nf = 0; nf < 8; nf++)
                #pragma unroll
                for (int r = 0; r < 4; r++) c[mf][nf][r] = 0.0f;

        unsigned aBase = sA + (warp_m * 32 + a_row) * ROWB + a_kof * 2;
        unsigned bBase = sB + (warp_n * 64 + b_row) * ROWB + b_kof * 2;

        #pragma unroll
        for (int ks = 0; ks < 8; ks++) {
            unsigned kb = ks * 32;
            unsigned a0[4], a1[4];
            ldmx4(a0[0], a0[1], a0[2], a0[3], aBase + kb);
            ldmx4(a1[0], a1[1], a1[2], a1[3], aBase + 16 * ROWB + kb);
            unsigned bf[8][2];
            #pragma unroll
            for (int bg = 0; bg < 4; bg++) {
                unsigned r0, r1, r2, r3;
                ldmx4(r0, r1, r2, r3, bBase + bg * 16 * ROWB + kb);
                bf[bg * 2 + 0][0] = r0; bf[bg * 2 + 0][1] = r1;
                bf[bg * 2 + 1][0] = r2; bf[bg * 2 + 1][1] = r3;
            }
            #pragma unroll
            for (int nf = 0; nf < 8; nf++) {
                mma_bf16(c[0][nf], a0, bf[nf][0], bf[nf][1]);
                mma_bf16(c[1][nf], a1, bf[nf][0], bf[nf][1]);
            }
        }
        __syncthreads();

        float th = tharr[p];
        int mrow = lane >> 2;
        int ncol = (lane & 3) * 2;
        #pragma unroll
        for (int mf = 0; mf < 2; mf++) {
            #pragma unroll
            for (int nf = 0; nf < 8; nf++) {
                #pragma unroll
                for (int r = 0; r < 4; r++) {
                    int ig = i0 + warp_m * 32 + mf * 16 + mrow + ((r >> 1) << 3);
                    int jg = j0 + warp_n * 64 + nf * 8 + ncol + (r & 1);
                    if (ig >= N || jg >= N) continue;
                    float v = c[mf][nf][r] * TAU_INV;
                    if (jg == ig) g_pos[p][ig] = v;
                    else if (v >= th) {
                        int q = atomicAdd(&g_cnt[p][ig], 1);
                        if (q < BUFC) g_buf[p][ig][q] = v; else g_flag[p][ig] = 1;
                    }
                }
            }
        }
    }
}

// ---------------- sorted-descending register insert ----------------
#define TK_INSERT(T, v)                                   \
    do { float _v = (v);                                  \
        _Pragma("unroll")                                 \
        for (int _k = 0; _k < KTOP; _k++) {               \
            float _t = T[_k];                             \
            T[_k] = fmaxf(_t, _v);                        \
            _v = fminf(_t, _v);                           \
        }                                                 \
    } while (0)

// ---- select + inline fallback + fused deterministic fixed-point reduction ----
__global__ void __launch_bounds__(256) k_select(float* __restrict__ out) {
    __shared__ long long ssum[256];
    __shared__ int flist[256];
    __shared__ int fcnt;
    int p = blockIdx.y;
    int N = clampN(g_N[p]);
    int tid = threadIdx.x;
    int i = blockIdx.x * 256 + tid;
    if (tid == 0) fcnt = 0;
    __syncthreads();

    long long my = 0;
    if (i < N) {
        int cnt = g_cnt[p][i];
        bool bad = g_flag[p][i] || cnt > BUFC || (cnt < KTOP && cnt < N - 1);
        if (bad) {
            int q = atomicAdd(&fcnt, 1);
            flist[q] = i;
        } else {
            const float* buf = g_buf[p][i];
            float T[KTOP];
            #pragma unroll
            for (int k = 0; k < KTOP; k++) T[k] = -INFINITY;
            for (int q = 0; q < cnt; q++) {
                float v = buf[q];
                if (v > T[KTOP - 1]) TK_INSERT(T, v);
            }
            float pos = g_pos[p][i];
            float m = fmaxf(pos, T[0]);
            float s = expf(pos - m);
            #pragma unroll
            for (int k = 0; k < KTOP; k++) s += expf(T[k] - m);
            float loss = m + logf(s) - pos;
            my = __double2ll_rn((double)loss * FXSCALE);
        }
    }
    __syncthreads();

    // warp-per-row exact recompute for flagged rows (expected: none)
    int nf = fcnt;
    int lane = tid & 31, wid = tid >> 5;
    for (int q = wid; q < nf; q += 8) {
        int i2 = flist[q];
        uint2 rs = ((const uint2*)(g_Zsb[p] + (size_t)i2 * D))[lane];
        __nv_bfloat162 s0 = *(__nv_bfloat162*)&rs.x, s1 = *(__nv_bfloat162*)&rs.y;
        float a0 = __low2float(s0), a1 = __high2float(s0);
        float a2 = __low2float(s1), a3 = __high2float(s1);
        float T[KTOP];
        #pragma unroll
        for (int k = 0; k < KTOP; k++) T[k] = -INFINITY;
        float pos = 0.0f;
        for (int j = 0; j < N; j++) {
            uint2 rw = ((const uint2*)(g_Zwb[p] + (size_t)j * D))[lane];
            __nv_bfloat162 w0 = *(__nv_bfloat162*)&rw.x, w1 = *(__nv_bfloat162*)&rw.y;
            float d = a0 * __low2float(w0) + a1 * __high2float(w0)
                    + a2 * __low2float(w1) + a3 * __high2float(w1);
            #pragma unroll
            for (int o = 16; o; o >>= 1) d += __shfl_xor_sync(0xffffffffu, d, o);
            d *= TAU_INV;
            if (j == i2) pos = d;
            else if (d > T[KTOP - 1]) TK_INSERT(T, d);
        }
        float m = fmaxf(pos, T[0]);
        float s = expf(pos - m);
        #pragma unroll
        for (int k = 0; k < KTOP; k++) s += expf(T[k] - m);
        if (lane == 0) {
            float loss = m + logf(s) - pos;
            my += __double2ll_rn((double)loss * FXSCALE);
        }
    }

    // block-wide integer reduction (deterministic) + one atomic per block
    ssum[tid] = my;
    __syncthreads();
    for (int o = 128; o; o >>= 1) {
        if (tid < o) ssum[tid] += ssum[tid + o];
        __syncthreads();
    }
    if (tid == 0) {
        if (ssum[0] != 0) atomicAdd(&g_lsum[p], (unsigned long long)ssum[0]);
        __threadfence();
        int nblocks = gridDim.x * gridDim.y;
        if (atomicAdd(&g_done, 1) == nblocks - 1) {
            __threadfence();
            double acc = 0.0;
            const double wgt[3] = {0.2, 1.0, 1.0};
            for (int q = 0; q < 3; q++) {
                int Nq = clampN(g_N[q]);
                if (Nq >= 4)
                    acc += wgt[q] * ((double)(long long)g_lsum[q] / FXSCALE / (double)Nq);
            }
            out[0] = (float)acc;
        }
    }
}

// ---------------- launch ----------------
extern "C" void kernel_launch(void* const* d_in, const int* in_sizes, int n_in,
                              void* d_out, int out_size) {
    const float* ev = (const float*)d_in[0];
    const float* ec = (const float*)d_in[1];
    const float* ep = (const float*)d_in[2];
    const void*  uv = d_in[3]; int nv  = in_sizes[3];
    const void*  uc = d_in[4]; int nc  = in_sizes[4];
    const void*  up = d_in[5]; int np_ = in_sizes[5];

    int nwmax = nv > nc ? nv : nc; if (np_ > nwmax) nwmax = np_;
    int nbuild = nc > np_ ? nc : np_;
    int nblk = (nwmax + CBS - 1) / CBS;

    static int attr_done = 0;
    if (!attr_done) {
        cudaFuncSetAttribute(k_gemm_mma,
                             cudaFuncAttributeMaxDynamicSharedMemorySize, SMEMB);
        attr_done = 1;
    }

    // pairs: (view->cart), (cart->purchase), (view->purchase)
    k_zero<<<64, 256>>>((const int*)uv, nv);
    k_build<<<(nbuild + 255) / 256, 256>>>(uc, nc, up, np_);
    k_compact<<<dim3(nblk, 3), CBS>>>(uv, nv, uc, nc, uv, nv);
    k_gather<<<dim3(NMAX / 8, 3), 256>>>(ev, ec, ep);
    k_gemm_mma<<<296, 256, SMEMB>>>();
    k_select<<<dim3(NMAX / 256, 3), 256>>>((float*)d_out);
}